// round 4
// baseline (speedup 1.0000x reference)
#include <cuda_runtime.h>
#include <cstdint>

// ---------------- problem constants ----------------
#define NMAX   50000
#define NPAD   50048            // padded to multiple of 64
#define EMAX   800000
#define FH     128              // hidden width (also W output width)
#define NHID   512
#define NOUT   256

// ---------------- device scratch (no allocs allowed) --------------
__device__ float g_hW [(size_t)NPAD * FH];   // GEMM output  (h @ W)
__device__ float g_c  [(size_t)NPAD * FH];   // conv output  (pre-bias)
__device__ float g_dis[NMAX];                // D^{-1/2}
__device__ int   g_cnt [NMAX];
__device__ int   g_off [NMAX + 1];
__device__ int   g_fill[NMAX];
__device__ int   g_srcs[EMAX];
__device__ float g_val [EMAX];
__device__ float g_pool[NOUT * FH];          // pooled graph features [G,128]
__device__ float g_m1  [NOUT * NHID];        // MLP hidden [G,512]

// ---------------- graph-prep kernels ----------------
__global__ void k_zero_cnt(int M) {
    int i = blockIdx.x * blockDim.x + threadIdx.x;
    if (i < M) g_cnt[i] = 0;
}

// edge_index is INT32 (JAX x64 disabled downcasts int64 -> int32)
__global__ void k_count(const int* __restrict__ ei, int E) {
    int e = blockIdx.x * blockDim.x + threadIdx.x;
    if (e < E) atomicAdd(&g_cnt[ei[E + e]], 1);
}

__global__ void k_dis(int M) {
    int i = blockIdx.x * blockDim.x + threadIdx.x;
    if (i < M) g_dis[i] = rsqrtf((float)(g_cnt[i] + 1));   // +1 self loop
}

// single-block exclusive scan of g_cnt -> g_off (and seeds g_fill)
__global__ void k_scan(int M) {
    __shared__ int sums[1024];
    int t = threadIdx.x;
    int chunk = (M + 1023) >> 10;
    int lo = t * chunk;
    int hi = lo + chunk; if (hi > M) hi = M;
    int s = 0;
    for (int i = lo; i < hi; i++) s += g_cnt[i];
    sums[t] = s;
    __syncthreads();
    for (int d = 1; d < 1024; d <<= 1) {
        int add = (t >= d) ? sums[t - d] : 0;
        __syncthreads();
        sums[t] += add;
        __syncthreads();
    }
    int run = sums[t] - s;     // exclusive prefix
    for (int i = lo; i < hi; i++) {
        g_off[i]  = run;
        g_fill[i] = run;
        run += g_cnt[i];
    }
    if (t == 1023) g_off[M] = sums[1023];
}

__global__ void k_fill(const int* __restrict__ ei, int E) {
    int e = blockIdx.x * blockDim.x + threadIdx.x;
    if (e < E) {
        int s = ei[e];
        int d = ei[E + e];
        int p = atomicAdd(&g_fill[d], 1);
        g_srcs[p] = s;
        g_val[p]  = g_dis[s] * g_dis[d];
    }
}

// ---------------- node GEMM:  g_hW = act(A) @ W --------------------
// A = external X (layer 0) or g_c with fused bias+ReLU (layers 1,2).
// 64 rows per block, 256 threads, full W staged in smem.
template <int K, bool FROM_C>
__global__ void __launch_bounds__(256, 2)
k_gemm(const float* __restrict__ X, const float* __restrict__ W,
       const float* __restrict__ bias, int M) {
    extern __shared__ float sm[];
    float* Ws = sm;                 // [K][128]
    float* As = sm + K * FH;        // [64][K]
    const float* A = FROM_C ? g_c : X;

    int t  = threadIdx.x;
    int m0 = blockIdx.x * 64;

    // stage W (K*128 floats)
    {
        const float4* W4  = (const float4*)W;
        float4*       Ws4 = (float4*)Ws;
        #pragma unroll
        for (int i = t; i < K * FH / 4; i += 256) Ws4[i] = W4[i];
    }
    // stage A tile with optional fused bias+ReLU
    {
        const int rw = K / 4;                 // float4 per row
        float4* As4 = (float4*)As;
        for (int i = t; i < 64 * rw; i += 256) {
            int r  = i / rw;
            int c4 = i - r * rw;
            int row = m0 + r;
            float4 v = make_float4(0.f, 0.f, 0.f, 0.f);
            if (row < M) v = *(const float4*)(A + (size_t)row * K + c4 * 4);
            if (FROM_C) {
                float4 b = ((const float4*)bias)[c4];
                v.x = fmaxf(v.x + b.x, 0.f);
                v.y = fmaxf(v.y + b.y, 0.f);
                v.z = fmaxf(v.z + b.z, 0.f);
                v.w = fmaxf(v.w + b.w, 0.f);
            }
            As4[i] = v;
        }
    }
    __syncthreads();

    int cg = t & 31;        // 32 column-groups of 4 cols
    int mg = t >> 5;        // 8 row-groups of 8 rows
    float acc[8][4];
    #pragma unroll
    for (int i = 0; i < 8; i++)
        #pragma unroll
        for (int j = 0; j < 4; j++) acc[i][j] = 0.f;

    const float* Ar = As + (size_t)(mg * 8) * K;
    #pragma unroll 2
    for (int k = 0; k < K; k++) {
        float4 w = ((const float4*)(Ws + k * FH))[cg];
        #pragma unroll
        for (int i = 0; i < 8; i++) {
            float a = Ar[i * K + k];          // warp-broadcast LDS
            acc[i][0] = fmaf(a, w.x, acc[i][0]);
            acc[i][1] = fmaf(a, w.y, acc[i][1]);
            acc[i][2] = fmaf(a, w.z, acc[i][2]);
            acc[i][3] = fmaf(a, w.w, acc[i][3]);
        }
    }

    #pragma unroll
    for (int i = 0; i < 8; i++) {
        int row = m0 + mg * 8 + i;
        if (row < M)
            *(float4*)(g_hW + (size_t)row * FH + cg * 4) =
                make_float4(acc[i][0], acc[i][1], acc[i][2], acc[i][3]);
    }
}

// ---------------- conv aggregation: g_c[dst] = sum_e norm_e * g_hW[src] ----
// one warp per destination node, 32 lanes x float4 = 128 features.
// Edge (idx,val) pairs loaded 32-at-a-time coalesced, distributed via shfl.
__global__ void k_conv(int M) {
    int warp = (blockIdx.x * blockDim.x + threadIdx.x) >> 5;
    if (warp >= M) return;
    int lane = threadIdx.x & 31;
    int node = warp;

    float d  = g_dis[node];
    float s0 = d * d;                                    // self-loop norm
    float4 h0 = *(const float4*)(g_hW + (size_t)node * FH + lane * 4);
    float4 acc = make_float4(s0 * h0.x, s0 * h0.y, s0 * h0.z, s0 * h0.w);

    int e  = g_off[node];
    int e1 = g_off[node + 1];
    while (e < e1) {
        int n = e1 - e; if (n > 32) n = 32;
        int   idx = 0;
        float v   = 0.f;
        if (lane < n) { idx = g_srcs[e + lane]; v = g_val[e + lane]; }
        for (int j = 0; j < n; j++) {
            int   s  = __shfl_sync(0xffffffffu, idx, j);
            float nv = __shfl_sync(0xffffffffu, v,   j);
            float4 h = *(const float4*)(g_hW + (size_t)s * FH + lane * 4);
            acc.x = fmaf(nv, h.x, acc.x);
            acc.y = fmaf(nv, h.y, acc.y);
            acc.z = fmaf(nv, h.z, acc.z);
            acc.w = fmaf(nv, h.w, acc.w);
        }
        e += n;
    }
    *(float4*)(g_c + (size_t)node * FH + lane * 4) = acc;
}

// ---------------- global mean pool (batch is sorted, int32) ----------------
__device__ __forceinline__ int lbound(const int* a, int n, int key) {
    int lo = 0, hi = n;
    while (lo < hi) {
        int mid = (lo + hi) >> 1;
        if (a[mid] < key) lo = mid + 1; else hi = mid;
    }
    return lo;
}

__global__ void k_pool(const int* __restrict__ batch,
                       const float* __restrict__ b2, int M) {
    int gi = blockIdx.x;
    int lo = lbound(batch, M, gi);
    int hi = lbound(batch, M, gi + 1);
    int f  = threadIdx.x;                                  // 128
    float s = 0.f;
    for (int i = lo; i < hi; i++) s += g_c[(size_t)i * FH + f];
    int cnt = hi - lo;
    g_pool[gi * FH + f] = (cnt > 0) ? s / (float)cnt + b2[f] : 0.f;
}

// ---------------- MLP head ----------------
__global__ void k_mlp1(const float* __restrict__ Wm1, const float* __restrict__ bm1) {
    __shared__ float gr[FH];
    int gi = blockIdx.x, t = threadIdx.x;                  // 512 threads
    if (t < FH) gr[t] = g_pool[gi * FH + t];
    __syncthreads();
    float s = bm1[t];
    #pragma unroll 8
    for (int k = 0; k < FH; k++) s = fmaf(gr[k], Wm1[k * NHID + t], s);
    g_m1[gi * NHID + t] = fmaxf(s, 0.f);
}

__global__ void k_mlp2(const float* __restrict__ Wm2, const float* __restrict__ bm2,
                       float* __restrict__ out) {
    __shared__ float gr[NHID];
    int gi = blockIdx.x, t = threadIdx.x;                  // 256 threads
    gr[t]       = g_m1[gi * NHID + t];
    gr[t + 256] = g_m1[gi * NHID + t + 256];
    __syncthreads();
    float s = bm2[t];
    #pragma unroll 8
    for (int k = 0; k < NHID; k++) s = fmaf(gr[k], Wm2[k * NOUT + t], s);
    out[gi * NOUT + t] = s;
}

// ---------------- launch ----------------
extern "C" void kernel_launch(void* const* d_in, const int* in_sizes, int n_in,
                              void* d_out, int out_size) {
    const float* x     = (const float*)d_in[0];
    const int*   ei    = (const int*)d_in[1];     // int32 (JAX x64 disabled)
    const int*   batch = (const int*)d_in[2];     // int32, sorted
    const float* W0  = (const float*)d_in[3];
    const float* b0  = (const float*)d_in[4];
    const float* W1  = (const float*)d_in[5];
    const float* b1  = (const float*)d_in[6];
    const float* W2  = (const float*)d_in[7];
    const float* b2  = (const float*)d_in[8];
    const float* Wm1 = (const float*)d_in[9];
    const float* bm1 = (const float*)d_in[10];
    const float* Wm2 = (const float*)d_in[11];
    const float* bm2 = (const float*)d_in[12];
    float* out = (float*)d_out;

    const int M = in_sizes[0] / 64;     // 50000 nodes
    const int E = in_sizes[1] / 2;      // 800000 edges
    const int G = out_size / NOUT;      // 256 graphs

    const int smem64  = (64  * FH + 64 * 64)  * 4;   // 48 KB
    const int smem128 = (128 * FH + 64 * 128) * 4;   // 96 KB
    static int attr_done = 0;
    if (!attr_done) {   // deterministic; set once outside capture
        cudaFuncSetAttribute(k_gemm<64,  false>, cudaFuncAttributeMaxDynamicSharedMemorySize, smem64);
        cudaFuncSetAttribute(k_gemm<128, true >, cudaFuncAttributeMaxDynamicSharedMemorySize, smem128);
        attr_done = 1;
    }

    const int TB = 256;
    int gbN = (M + TB - 1) / TB;
    int gbE = (E + TB - 1) / TB;
    int gbG = (M + 63) / 64;            // GEMM blocks (64 rows each)
    int gbC = (M + 7) / 8;              // conv blocks (8 warps each)

    // graph prep: degree -> dis -> CSR
    k_zero_cnt<<<gbN, TB>>>(M);
    k_count   <<<gbE, TB>>>(ei, E);
    k_dis     <<<gbN, TB>>>(M);
    k_scan    <<<1, 1024>>>(M);
    k_fill    <<<gbE, TB>>>(ei, E);

    // layer 0: hW = x @ W0 ; c = A_hat hW
    k_gemm<64,  false><<<gbG, TB, smem64 >>>(x, W0, nullptr, M);
    k_conv<<<gbC, TB>>>(M);
    // layer 1: hW = relu(c + b0) @ W1 ; c = A_hat hW
    k_gemm<128, true ><<<gbG, TB, smem128>>>(nullptr, W1, b0, M);
    k_conv<<<gbC, TB>>>(M);
    // layer 2: hW = relu(c + b1) @ W2 ; c = A_hat hW
    k_gemm<128, true ><<<gbG, TB, smem128>>>(nullptr, W2, b1, M);
    k_conv<<<gbC, TB>>>(M);

    // pool (+b2 fused) and MLP head
    k_pool<<<G, FH>>>(batch, b2, M);
    k_mlp1<<<G, NHID>>>(Wm1, bm1);
    k_mlp2<<<G, NOUT>>>(Wm2, bm2, out);
}

// round 5
// speedup vs baseline: 1.2271x; 1.2271x over previous
#include <cuda_runtime.h>
#include <cstdint>

// ---------------- problem constants ----------------
#define NMAX   50000
#define NPAD   50048            // padded to multiple of 64
#define EMAX   800000
#define FH     128              // hidden width (also W output width)
#define NHID   512
#define NOUT   256
#define SCAN_B 256              // elements per scan block
#define SCAN_NB ((NMAX + SCAN_B - 1) / SCAN_B)   // 196

// ---------------- device scratch (no allocs allowed) --------------
__device__ float g_hW [(size_t)NPAD * FH];   // GEMM output  (h @ W)
__device__ float g_c  [(size_t)NPAD * FH];   // conv output  (pre-bias)
__device__ float g_dis[NMAX];                // D^{-1/2}
__device__ int   g_cnt [NMAX];
__device__ int   g_off [NMAX + 1];
__device__ int   g_fill[NMAX];
__device__ int   g_part[SCAN_B];             // per-block partial sums (>=196)
__device__ int   g_srcs[EMAX];
__device__ float g_val [EMAX];
__device__ float g_pool[NOUT * FH];          // pooled graph features [G,128]
__device__ float g_m1  [NOUT * NHID];        // MLP hidden [G,512]

// ---------------- graph-prep kernels ----------------
__global__ void k_zero_cnt(int M) {
    int i = blockIdx.x * blockDim.x + threadIdx.x;
    if (i < M) g_cnt[i] = 0;
}

// edge_index is INT32 (JAX x64 disabled downcasts int64 -> int32)
__global__ void k_count(const int* __restrict__ ei, int E) {
    int e = blockIdx.x * blockDim.x + threadIdx.x;
    if (e < E) atomicAdd(&g_cnt[ei[E + e]], 1);
}

__global__ void k_dis(int M) {
    int i = blockIdx.x * blockDim.x + threadIdx.x;
    if (i < M) g_dis[i] = rsqrtf((float)(g_cnt[i] + 1));   // +1 self loop
}

// ---- grid-wide exclusive scan of g_cnt -> g_off (3 phases) ----
// phase 1: per-block sums
__global__ void k_scan1(int M) {
    __shared__ int red[SCAN_B];
    int t = threadIdx.x;
    int i = blockIdx.x * SCAN_B + t;
    int v = (i < M) ? g_cnt[i] : 0;
    red[t] = v;
    __syncthreads();
    for (int d = SCAN_B / 2; d > 0; d >>= 1) {
        if (t < d) red[t] += red[t + d];
        __syncthreads();
    }
    if (t == 0) g_part[blockIdx.x] = red[0];
}

// phase 2: exclusive scan of partials (1 block), writes g_off[M]
__global__ void k_scan2(int nb, int M) {
    __shared__ int sm[SCAN_B];
    int t = threadIdx.x;
    int v = (t < nb) ? g_part[t] : 0;
    sm[t] = v;
    __syncthreads();
    for (int d = 1; d < SCAN_B; d <<= 1) {
        int add = (t >= d) ? sm[t - d] : 0;
        __syncthreads();
        sm[t] += add;
        __syncthreads();
    }
    if (t < nb) g_part[t] = sm[t] - v;          // exclusive
    if (t == SCAN_B - 1) g_off[M] = sm[SCAN_B - 1];
}

// phase 3: block-local exclusive scan + base, writes g_off & g_fill
__global__ void k_scan3(int M) {
    __shared__ int sm[SCAN_B];
    int t = threadIdx.x;
    int i = blockIdx.x * SCAN_B + t;
    int v = (i < M) ? g_cnt[i] : 0;
    sm[t] = v;
    __syncthreads();
    for (int d = 1; d < SCAN_B; d <<= 1) {
        int add = (t >= d) ? sm[t - d] : 0;
        __syncthreads();
        sm[t] += add;
        __syncthreads();
    }
    if (i < M) {
        int excl = g_part[blockIdx.x] + sm[t] - v;
        g_off[i]  = excl;
        g_fill[i] = excl;
    }
}

__global__ void k_fill(const int* __restrict__ ei, int E) {
    int e = blockIdx.x * blockDim.x + threadIdx.x;
    if (e < E) {
        int s = ei[e];
        int d = ei[E + e];
        int p = atomicAdd(&g_fill[d], 1);
        g_srcs[p] = s;
        g_val[p]  = g_dis[s] * g_dis[d];
    }
}

// ---------------- node GEMM:  g_hW = act(A) @ W --------------------
// A = external X (layer 0) or g_c with fused bias+ReLU (layers 1,2).
// 64 rows per block, 256 threads, full W staged in smem.
template <int K, bool FROM_C>
__global__ void __launch_bounds__(256, 2)
k_gemm(const float* __restrict__ X, const float* __restrict__ W,
       const float* __restrict__ bias, int M) {
    extern __shared__ float sm[];
    float* Ws = sm;                 // [K][128]
    float* As = sm + K * FH;        // [64][K]
    const float* A = FROM_C ? g_c : X;

    int t  = threadIdx.x;
    int m0 = blockIdx.x * 64;

    // stage W (K*128 floats)
    {
        const float4* W4  = (const float4*)W;
        float4*       Ws4 = (float4*)Ws;
        #pragma unroll
        for (int i = t; i < K * FH / 4; i += 256) Ws4[i] = W4[i];
    }
    // stage A tile with optional fused bias+ReLU
    {
        const int rw = K / 4;                 // float4 per row
        float4* As4 = (float4*)As;
        for (int i = t; i < 64 * rw; i += 256) {
            int r  = i / rw;
            int c4 = i - r * rw;
            int row = m0 + r;
            float4 v = make_float4(0.f, 0.f, 0.f, 0.f);
            if (row < M) v = *(const float4*)(A + (size_t)row * K + c4 * 4);
            if (FROM_C) {
                float4 b = ((const float4*)bias)[c4];
                v.x = fmaxf(v.x + b.x, 0.f);
                v.y = fmaxf(v.y + b.y, 0.f);
                v.z = fmaxf(v.z + b.z, 0.f);
                v.w = fmaxf(v.w + b.w, 0.f);
            }
            As4[i] = v;
        }
    }
    __syncthreads();

    int cg = t & 31;        // 32 column-groups of 4 cols
    int mg = t >> 5;        // 8 row-groups of 8 rows
    float acc[8][4];
    #pragma unroll
    for (int i = 0; i < 8; i++)
        #pragma unroll
        for (int j = 0; j < 4; j++) acc[i][j] = 0.f;

    const float* Ar = As + (size_t)(mg * 8) * K;
    #pragma unroll 2
    for (int k = 0; k < K; k++) {
        float4 w = ((const float4*)(Ws + k * FH))[cg];
        #pragma unroll
        for (int i = 0; i < 8; i++) {
            float a = Ar[i * K + k];          // warp-broadcast LDS
            acc[i][0] = fmaf(a, w.x, acc[i][0]);
            acc[i][1] = fmaf(a, w.y, acc[i][1]);
            acc[i][2] = fmaf(a, w.z, acc[i][2]);
            acc[i][3] = fmaf(a, w.w, acc[i][3]);
        }
    }

    #pragma unroll
    for (int i = 0; i < 8; i++) {
        int row = m0 + mg * 8 + i;
        if (row < M)
            *(float4*)(g_hW + (size_t)row * FH + cg * 4) =
                make_float4(acc[i][0], acc[i][1], acc[i][2], acc[i][3]);
    }
}

// ---------------- conv aggregation: g_c[dst] = sum_e norm_e * g_hW[src] ----
// one warp per destination node, 32 lanes x float4 = 128 features.
__global__ void k_conv(int M) {
    int warp = (blockIdx.x * blockDim.x + threadIdx.x) >> 5;
    if (warp >= M) return;
    int lane = threadIdx.x & 31;
    int node = warp;

    float d  = g_dis[node];
    float s0 = d * d;                                    // self-loop norm
    float4 h0 = *(const float4*)(g_hW + (size_t)node * FH + lane * 4);
    float4 acc = make_float4(s0 * h0.x, s0 * h0.y, s0 * h0.z, s0 * h0.w);

    int e  = g_off[node];
    int e1 = g_off[node + 1];
    while (e < e1) {
        int n = e1 - e; if (n > 32) n = 32;
        int   idx = 0;
        float v   = 0.f;
        if (lane < n) { idx = g_srcs[e + lane]; v = g_val[e + lane]; }
        for (int j = 0; j < n; j++) {
            int   s  = __shfl_sync(0xffffffffu, idx, j);
            float nv = __shfl_sync(0xffffffffu, v,   j);
            float4 h = *(const float4*)(g_hW + (size_t)s * FH + lane * 4);
            acc.x = fmaf(nv, h.x, acc.x);
            acc.y = fmaf(nv, h.y, acc.y);
            acc.z = fmaf(nv, h.z, acc.z);
            acc.w = fmaf(nv, h.w, acc.w);
        }
        e += n;
    }
    *(float4*)(g_c + (size_t)node * FH + lane * 4) = acc;
}

// ---------------- global mean pool (batch is sorted, int32) ----------------
__device__ __forceinline__ int lbound(const int* a, int n, int key) {
    int lo = 0, hi = n;
    while (lo < hi) {
        int mid = (lo + hi) >> 1;
        if (a[mid] < key) lo = mid + 1; else hi = mid;
    }
    return lo;
}

__global__ void k_pool(const int* __restrict__ batch,
                       const float* __restrict__ b2, int M) {
    int gi = blockIdx.x;
    int lo = lbound(batch, M, gi);
    int hi = lbound(batch, M, gi + 1);
    int f  = threadIdx.x;                                  // 128
    float s = 0.f;
    for (int i = lo; i < hi; i++) s += g_c[(size_t)i * FH + f];
    int cnt = hi - lo;
    g_pool[gi * FH + f] = (cnt > 0) ? s / (float)cnt + b2[f] : 0.f;
}

// ---------------- MLP head ----------------
__global__ void k_mlp1(const float* __restrict__ Wm1, const float* __restrict__ bm1) {
    __shared__ float gr[FH];
    int gi = blockIdx.x, t = threadIdx.x;                  // 512 threads
    if (t < FH) gr[t] = g_pool[gi * FH + t];
    __syncthreads();
    float s = bm1[t];
    #pragma unroll 8
    for (int k = 0; k < FH; k++) s = fmaf(gr[k], Wm1[k * NHID + t], s);
    g_m1[gi * NHID + t] = fmaxf(s, 0.f);
}

__global__ void k_mlp2(const float* __restrict__ Wm2, const float* __restrict__ bm2,
                       float* __restrict__ out) {
    __shared__ float gr[NHID];
    int gi = blockIdx.x, t = threadIdx.x;                  // 256 threads
    gr[t]       = g_m1[gi * NHID + t];
    gr[t + 256] = g_m1[gi * NHID + t + 256];
    __syncthreads();
    float s = bm2[t];
    #pragma unroll 8
    for (int k = 0; k < NHID; k++) s = fmaf(gr[k], Wm2[k * NOUT + t], s);
    out[gi * NOUT + t] = s;
}

// ---------------- launch ----------------
extern "C" void kernel_launch(void* const* d_in, const int* in_sizes, int n_in,
                              void* d_out, int out_size) {
    const float* x     = (const float*)d_in[0];
    const int*   ei    = (const int*)d_in[1];     // int32 (JAX x64 disabled)
    const int*   batch = (const int*)d_in[2];     // int32, sorted
    const float* W0  = (const float*)d_in[3];
    const float* b0  = (const float*)d_in[4];
    const float* W1  = (const float*)d_in[5];
    const float* b1  = (const float*)d_in[6];
    const float* W2  = (const float*)d_in[7];
    const float* b2  = (const float*)d_in[8];
    const float* Wm1 = (const float*)d_in[9];
    const float* bm1 = (const float*)d_in[10];
    const float* Wm2 = (const float*)d_in[11];
    const float* bm2 = (const float*)d_in[12];
    float* out = (float*)d_out;

    const int M = in_sizes[0] / 64;     // 50000 nodes
    const int E = in_sizes[1] / 2;      // 800000 edges
    const int G = out_size / NOUT;      // 256 graphs

    const int smem64  = (64  * FH + 64 * 64)  * 4;   // 48 KB
    const int smem128 = (128 * FH + 64 * 128) * 4;   // 96 KB
    static int attr_done = 0;
    if (!attr_done) {
        cudaFuncSetAttribute(k_gemm<64,  false>, cudaFuncAttributeMaxDynamicSharedMemorySize, smem64);
        cudaFuncSetAttribute(k_gemm<128, true >, cudaFuncAttributeMaxDynamicSharedMemorySize, smem128);
        attr_done = 1;
    }

    const int TB = 256;
    int gbN = (M + TB - 1) / TB;
    int gbE = (E + TB - 1) / TB;
    int gbS = (M + SCAN_B - 1) / SCAN_B;   // scan blocks
    int gbG = (M + 63) / 64;               // GEMM blocks (64 rows each)
    int gbC = (M + 7) / 8;                 // conv blocks (8 warps each)

    // graph prep: degree -> dis -> CSR (grid-wide 3-phase scan)
    k_zero_cnt<<<gbN, TB>>>(M);
    k_count   <<<gbE, TB>>>(ei, E);
    k_dis     <<<gbN, TB>>>(M);
    k_scan1   <<<gbS, SCAN_B>>>(M);
    k_scan2   <<<1,   SCAN_B>>>(gbS, M);
    k_scan3   <<<gbS, SCAN_B>>>(M);
    k_fill    <<<gbE, TB>>>(ei, E);

    // layer 0: hW = x @ W0 ; c = A_hat hW
    k_gemm<64,  false><<<gbG, TB, smem64 >>>(x, W0, nullptr, M);
    k_conv<<<gbC, TB>>>(M);
    // layer 1: hW = relu(c + b0) @ W1 ; c = A_hat hW
    k_gemm<128, true ><<<gbG, TB, smem128>>>(nullptr, W1, b0, M);
    k_conv<<<gbC, TB>>>(M);
    // layer 2: hW = relu(c + b1) @ W2 ; c = A_hat hW
    k_gemm<128, true ><<<gbG, TB, smem128>>>(nullptr, W2, b1, M);
    k_conv<<<gbC, TB>>>(M);

    // pool (+b2 fused) and MLP head
    k_pool<<<G, FH>>>(batch, b2, M);
    k_mlp1<<<G, NHID>>>(Wm1, bm1);
    k_mlp2<<<G, NOUT>>>(Wm2, bm2, out);
}

// round 6
// speedup vs baseline: 1.3028x; 1.0617x over previous
#include <cuda_runtime.h>
#include <cstdint>

// ---------------- problem constants ----------------
#define NMAX   50000
#define NPAD   50048
#define EMAX   800000
#define FH     128
#define NHID   512
#define NOUT   256
#define SCAN_B 256
// scan blocks = ceil(50000/256) = 196  (must be <= SCAN_B)

// ---------------- device scratch (no allocs allowed) --------------
__device__ float g_hW [(size_t)NPAD * FH];
__device__ float g_c  [(size_t)NPAD * FH];
__device__ float g_dis[NMAX];
__device__ int   g_cnt [NMAX];
__device__ int   g_off [NMAX + 1];
__device__ int   g_fill[NMAX];
__device__ int   g_part[SCAN_B];
__device__ int   g_srcs[EMAX];
__device__ float g_val [EMAX];
__device__ float g_pool[NOUT * FH];
__device__ float g_m1  [NOUT * NHID];

// ---------------- f32x2 packed-FMA helpers ----------------
__device__ __forceinline__ unsigned long long pack2(float x, float y) {
    unsigned long long r;
    asm("mov.b64 %0, {%1, %2};" : "=l"(r) : "f"(x), "f"(y));
    return r;
}
__device__ __forceinline__ unsigned long long ffma2(
        unsigned long long a, unsigned long long b, unsigned long long c) {
    unsigned long long d;
    asm("fma.rn.f32x2 %0, %1, %2, %3;" : "=l"(d) : "l"(a), "l"(b), "l"(c));
    return d;
}

// ---------------- graph-prep kernels ----------------
// edge_index is INT32 (JAX x64 disabled downcasts int64 -> int32)
__global__ void k_count(const int* __restrict__ ei, int E) {
    int e = blockIdx.x * blockDim.x + threadIdx.x;
    if (e < E) atomicAdd(&g_cnt[ei[E + e]], 1);
}

// per-block sums of g_cnt + fused D^{-1/2}
__global__ void k_scan1(int M) {
    __shared__ int red[SCAN_B];
    int t = threadIdx.x;
    int i = blockIdx.x * SCAN_B + t;
    int v = (i < M) ? g_cnt[i] : 0;
    if (i < M) g_dis[i] = rsqrtf((float)(v + 1));      // +1 self loop
    red[t] = v;
    __syncthreads();
    for (int d = SCAN_B / 2; d > 0; d >>= 1) {
        if (t < d) red[t] += red[t + d];
        __syncthreads();
    }
    if (t == 0) g_part[blockIdx.x] = red[0];
}

// fused: every block scans ALL partials locally (nb<=256), then local scan
__global__ void k_scan23(int M, int nb) {
    __shared__ int sm[SCAN_B];
    int t = threadIdx.x, bid = blockIdx.x;
    // phase A: inclusive scan of partials
    int pv = (t < nb) ? g_part[t] : 0;
    sm[t] = pv;
    __syncthreads();
    for (int d = 1; d < SCAN_B; d <<= 1) {
        int add = (t >= d) ? sm[t - d] : 0;
        __syncthreads();
        sm[t] += add;
        __syncthreads();
    }
    int base = sm[bid] - g_part[bid];      // exclusive prefix of this block
    int total = sm[SCAN_B - 1];
    __syncthreads();
    // phase B: local inclusive scan of this block's counts
    int i = bid * SCAN_B + t;
    int v = (i < M) ? g_cnt[i] : 0;
    sm[t] = v;
    __syncthreads();
    for (int d = 1; d < SCAN_B; d <<= 1) {
        int add = (t >= d) ? sm[t - d] : 0;
        __syncthreads();
        sm[t] += add;
        __syncthreads();
    }
    if (i < M) {
        int ex = base + sm[t] - v;
        g_off[i]  = ex;
        g_fill[i] = ex;
    }
    if (bid == 0 && t == 0) g_off[M] = total;
}

__global__ void k_fill(const int* __restrict__ ei, int E) {
    int e = blockIdx.x * blockDim.x + threadIdx.x;
    if (e < E) {
        int s = ei[e];
        int d = ei[E + e];
        int p = atomicAdd(&g_fill[d], 1);
        g_srcs[p] = s;
        g_val[p]  = g_dis[s] * g_dis[d];
    }
}

// ---------------- node GEMM:  g_hW = act(A) @ W  (f32x2 packed FMA) -------
template <int K, bool FROM_C>
__global__ void __launch_bounds__(256, 2)
k_gemm(const float* __restrict__ X, const float* __restrict__ W,
       const float* __restrict__ bias, int M) {
    extern __shared__ float sm[];
    float* Ws = sm;                 // [K][128]
    float* As = sm + K * FH;        // [64][K]
    const float* A = FROM_C ? g_c : X;

    int t  = threadIdx.x;
    int m0 = blockIdx.x * 64;

    {   // stage W
        const float4* W4  = (const float4*)W;
        float4*       Ws4 = (float4*)Ws;
        #pragma unroll
        for (int i = t; i < K * FH / 4; i += 256) Ws4[i] = W4[i];
    }
    {   // stage A tile with optional fused bias+ReLU
        const int rw = K / 4;
        float4* As4 = (float4*)As;
        for (int i = t; i < 64 * rw; i += 256) {
            int r  = i / rw;
            int c4 = i - r * rw;
            int row = m0 + r;
            float4 v = make_float4(0.f, 0.f, 0.f, 0.f);
            if (row < M) v = *(const float4*)(A + (size_t)row * K + c4 * 4);
            if (FROM_C) {
                float4 b = ((const float4*)bias)[c4];
                v.x = fmaxf(v.x + b.x, 0.f);
                v.y = fmaxf(v.y + b.y, 0.f);
                v.z = fmaxf(v.z + b.z, 0.f);
                v.w = fmaxf(v.w + b.w, 0.f);
            }
            As4[i] = v;
        }
    }
    __syncthreads();

    int cg = t & 31;        // 32 column-groups of 4 cols
    int mg = t >> 5;        // 8 row-groups of 8 rows
    unsigned long long acc2[8][2];
    #pragma unroll
    for (int i = 0; i < 8; i++) { acc2[i][0] = 0ull; acc2[i][1] = 0ull; }

    const float* Ar = As + (size_t)(mg * 8) * K;
    #pragma unroll 2
    for (int k = 0; k < K; k++) {
        ulonglong2 w = ((const ulonglong2*)(Ws + k * FH))[cg];  // 4 cols packed
        #pragma unroll
        for (int i = 0; i < 8; i++) {
            float a = Ar[i * K + k];                  // warp-broadcast LDS
            unsigned long long aa = pack2(a, a);
            acc2[i][0] = ffma2(aa, w.x, acc2[i][0]);
            acc2[i][1] = ffma2(aa, w.y, acc2[i][1]);
        }
    }

    #pragma unroll
    for (int i = 0; i < 8; i++) {
        int row = m0 + mg * 8 + i;
        if (row < M)
            ((ulonglong2*)(g_hW + (size_t)row * FH))[cg] =
                make_ulonglong2(acc2[i][0], acc2[i][1]);
    }
}

// ---------------- conv: g_c[dst] = sum_e norm_e * g_hW[src]  ------------
// one warp per node, 32 lanes x float4; 4-wide unroll for MLP.
__global__ void k_conv(int M) {
    int warp = (blockIdx.x * blockDim.x + threadIdx.x) >> 5;
    if (warp >= M) return;
    int lane = threadIdx.x & 31;
    int node = warp;

    float d  = g_dis[node];
    float s0 = d * d;
    float4 h0 = *(const float4*)(g_hW + (size_t)node * FH + lane * 4);
    float4 acc = make_float4(s0 * h0.x, s0 * h0.y, s0 * h0.z, s0 * h0.w);

    int e  = g_off[node];
    int e1 = g_off[node + 1];
    while (e < e1) {
        int n = e1 - e; if (n > 32) n = 32;
        int   idx = 0;
        float v   = 0.f;
        if (lane < n) { idx = g_srcs[e + lane]; v = g_val[e + lane]; }
        int j = 0;
        for (; j + 4 <= n; j += 4) {                      // 4 gathers in flight
            int   sA = __shfl_sync(0xffffffffu, idx, j);
            int   sB = __shfl_sync(0xffffffffu, idx, j + 1);
            int   sC = __shfl_sync(0xffffffffu, idx, j + 2);
            int   sD = __shfl_sync(0xffffffffu, idx, j + 3);
            float vA = __shfl_sync(0xffffffffu, v, j);
            float vB = __shfl_sync(0xffffffffu, v, j + 1);
            float vC = __shfl_sync(0xffffffffu, v, j + 2);
            float vD = __shfl_sync(0xffffffffu, v, j + 3);
            float4 hA = *(const float4*)(g_hW + (size_t)sA * FH + lane * 4);
            float4 hB = *(const float4*)(g_hW + (size_t)sB * FH + lane * 4);
            float4 hC = *(const float4*)(g_hW + (size_t)sC * FH + lane * 4);
            float4 hD = *(const float4*)(g_hW + (size_t)sD * FH + lane * 4);
            acc.x = fmaf(vA, hA.x, acc.x); acc.y = fmaf(vA, hA.y, acc.y);
            acc.z = fmaf(vA, hA.z, acc.z); acc.w = fmaf(vA, hA.w, acc.w);
            acc.x = fmaf(vB, hB.x, acc.x); acc.y = fmaf(vB, hB.y, acc.y);
            acc.z = fmaf(vB, hB.z, acc.z); acc.w = fmaf(vB, hB.w, acc.w);
            acc.x = fmaf(vC, hC.x, acc.x); acc.y = fmaf(vC, hC.y, acc.y);
            acc.z = fmaf(vC, hC.z, acc.z); acc.w = fmaf(vC, hC.w, acc.w);
            acc.x = fmaf(vD, hD.x, acc.x); acc.y = fmaf(vD, hD.y, acc.y);
            acc.z = fmaf(vD, hD.z, acc.z); acc.w = fmaf(vD, hD.w, acc.w);
        }
        for (; j < n; j++) {
            int   s  = __shfl_sync(0xffffffffu, idx, j);
            float nv = __shfl_sync(0xffffffffu, v, j);
            float4 h = *(const float4*)(g_hW + (size_t)s * FH + lane * 4);
            acc.x = fmaf(nv, h.x, acc.x);
            acc.y = fmaf(nv, h.y, acc.y);
            acc.z = fmaf(nv, h.z, acc.z);
            acc.w = fmaf(nv, h.w, acc.w);
        }
        e += n;
    }
    *(float4*)(g_c + (size_t)node * FH + lane * 4) = acc;
}

// ---------------- global mean pool (batch sorted, int32) ----------------
__device__ __forceinline__ int lbound(const int* a, int n, int key) {
    int lo = 0, hi = n;
    while (lo < hi) {
        int mid = (lo + hi) >> 1;
        if (a[mid] < key) lo = mid + 1; else hi = mid;
    }
    return lo;
}

__global__ void k_pool(const int* __restrict__ batch,
                       const float* __restrict__ b2, int M) {
    int gi = blockIdx.x;
    int lo = lbound(batch, M, gi);
    int hi = lbound(batch, M, gi + 1);
    int f  = threadIdx.x;                                  // 128
    float s = 0.f;
    for (int i = lo; i < hi; i++) s += g_c[(size_t)i * FH + f];
    int cnt = hi - lo;
    g_pool[gi * FH + f] = (cnt > 0) ? s / (float)cnt + b2[f] : 0.f;
}

// ---------------- MLP head ----------------
__global__ void k_mlp1(const float* __restrict__ Wm1, const float* __restrict__ bm1) {
    __shared__ float gr[FH];
    int gi = blockIdx.x, t = threadIdx.x;                  // 512
    if (t < FH) gr[t] = g_pool[gi * FH + t];
    __syncthreads();
    float s = bm1[t];
    #pragma unroll 8
    for (int k = 0; k < FH; k++) s = fmaf(gr[k], Wm1[k * NHID + t], s);
    g_m1[gi * NHID + t] = fmaxf(s, 0.f);
}

__global__ void k_mlp2(const float* __restrict__ Wm2, const float* __restrict__ bm2,
                       float* __restrict__ out) {
    __shared__ float gr[NHID];
    int gi = blockIdx.x, t = threadIdx.x;                  // 256
    gr[t]       = g_m1[gi * NHID + t];
    gr[t + 256] = g_m1[gi * NHID + t + 256];
    __syncthreads();
    float s = bm2[t];
    #pragma unroll 8
    for (int k = 0; k < NHID; k++) s = fmaf(gr[k], Wm2[k * NOUT + t], s);
    out[gi * NOUT + t] = s;
}

// ---------------- launch ----------------
extern "C" void kernel_launch(void* const* d_in, const int* in_sizes, int n_in,
                              void* d_out, int out_size) {
    const float* x     = (const float*)d_in[0];
    const int*   ei    = (const int*)d_in[1];
    const int*   batch = (const int*)d_in[2];
    const float* W0  = (const float*)d_in[3];
    const float* b0  = (const float*)d_in[4];
    const float* W1  = (const float*)d_in[5];
    const float* b1  = (const float*)d_in[6];
    const float* W2  = (const float*)d_in[7];
    const float* b2  = (const float*)d_in[8];
    const float* Wm1 = (const float*)d_in[9];
    const float* bm1 = (const float*)d_in[10];
    const float* Wm2 = (const float*)d_in[11];
    const float* bm2 = (const float*)d_in[12];
    float* out = (float*)d_out;

    const int M = in_sizes[0] / 64;     // 50000 nodes
    const int E = in_sizes[1] / 2;      // 800000 edges
    const int G = out_size / NOUT;      // 256 graphs

    const int smem64  = (64  * FH + 64 * 64)  * 4;   // 48 KB
    const int smem128 = (128 * FH + 64 * 128) * 4;   // 96 KB
    static void* cnt_ptr = nullptr;
    if (!cnt_ptr) {
        cudaFuncSetAttribute(k_gemm<64,  false>, cudaFuncAttributeMaxDynamicSharedMemorySize, smem64);
        cudaFuncSetAttribute(k_gemm<128, true >, cudaFuncAttributeMaxDynamicSharedMemorySize, smem128);
        cudaGetSymbolAddress(&cnt_ptr, g_cnt);
    }

    const int TB = 256;
    int gbE = (E + TB - 1) / TB;
    int gbS = (M + SCAN_B - 1) / SCAN_B;   // 196
    int gbG = (M + 63) / 64;
    int gbC = (M + 7) / 8;

    // graph prep (memset is a graph node, not a kernel -> keeps ncu -s aim)
    cudaMemsetAsync(cnt_ptr, 0, (size_t)M * sizeof(int));
    k_count <<<gbE, TB>>>(ei, E);          // kernel 0
    k_scan1 <<<gbS, SCAN_B>>>(M);          // kernel 1 (+dis)
    k_scan23<<<gbS, SCAN_B>>>(M, gbS);     // kernel 2
    k_fill  <<<gbE, TB>>>(ei, E);          // kernel 3

    // layer 0
    k_gemm<64,  false><<<gbG, TB, smem64 >>>(x, W0, nullptr, M);  // kernel 4
    k_conv<<<gbC, TB>>>(M);                                       // kernel 5 <- ncu
    // layer 1
    k_gemm<128, true ><<<gbG, TB, smem128>>>(nullptr, W1, b0, M);
    k_conv<<<gbC, TB>>>(M);
    // layer 2
    k_gemm<128, true ><<<gbG, TB, smem128>>>(nullptr, W2, b1, M);
    k_conv<<<gbC, TB>>>(M);

    // pool + MLP head
    k_pool<<<G, FH>>>(batch, b2, M);
    k_mlp1<<<G, NHID>>>(Wm1, bm1);
    k_mlp2<<<G, NOUT>>>(Wm2, bm2, out);
}

// round 7
// speedup vs baseline: 1.5846x; 1.2163x over previous
#include <cuda_runtime.h>
#include <cuda_fp16.h>
#include <cstdint>

// ---------------- problem constants ----------------
#define NMAX   50000
#define NPAD   50048
#define EMAX   800000
#define FH     128
#define NHID   512
#define NOUT   256
#define SCAN_B 256

// ---------------- device scratch (no allocs allowed) --------------
__device__ __half g_hWh[(size_t)NPAD * FH];  // GEMM output in fp16 (gather source)
__device__ float  g_c  [(size_t)NPAD * FH];  // conv output fp32
__device__ float  g_dis[NMAX];
__device__ int    g_cnt [NMAX];
__device__ int    g_off [NMAX + 1];
__device__ int    g_fill[NMAX];
__device__ int    g_part[SCAN_B];
__device__ int    g_srcs[EMAX];
__device__ float  g_val [EMAX];
__device__ float  g_pool[NOUT * FH];
__device__ float  g_m1  [NOUT * NHID];

// ---------------- f32x2 packed-FMA helpers ----------------
__device__ __forceinline__ unsigned long long pack2(float x, float y) {
    unsigned long long r;
    asm("mov.b64 %0, {%1, %2};" : "=l"(r) : "f"(x), "f"(y));
    return r;
}
__device__ __forceinline__ void unpack2(unsigned long long p, float& x, float& y) {
    asm("mov.b64 {%0, %1}, %2;" : "=f"(x), "=f"(y) : "l"(p));
}
__device__ __forceinline__ unsigned long long ffma2(
        unsigned long long a, unsigned long long b, unsigned long long c) {
    unsigned long long d;
    asm("fma.rn.f32x2 %0, %1, %2, %3;" : "=l"(d) : "l"(a), "l"(b), "l"(c));
    return d;
}

// ---------------- graph-prep kernels ----------------
__global__ void k_count(const int* __restrict__ ei, int E) {
    int e = blockIdx.x * blockDim.x + threadIdx.x;
    if (e < E) atomicAdd(&g_cnt[ei[E + e]], 1);
}

__global__ void k_scan1(int M) {
    __shared__ int red[SCAN_B];
    int t = threadIdx.x;
    int i = blockIdx.x * SCAN_B + t;
    int v = (i < M) ? g_cnt[i] : 0;
    if (i < M) g_dis[i] = rsqrtf((float)(v + 1));      // +1 self loop
    red[t] = v;
    __syncthreads();
    for (int d = SCAN_B / 2; d > 0; d >>= 1) {
        if (t < d) red[t] += red[t + d];
        __syncthreads();
    }
    if (t == 0) g_part[blockIdx.x] = red[0];
}

__global__ void k_scan23(int M, int nb) {
    __shared__ int sm[SCAN_B];
    int t = threadIdx.x, bid = blockIdx.x;
    int pv = (t < nb) ? g_part[t] : 0;
    sm[t] = pv;
    __syncthreads();
    for (int d = 1; d < SCAN_B; d <<= 1) {
        int add = (t >= d) ? sm[t - d] : 0;
        __syncthreads();
        sm[t] += add;
        __syncthreads();
    }
    int base  = sm[bid] - pv * 0 - g_part[bid] + pv - pv; // = sm[bid]-g_part[bid]
    base = sm[bid] - g_part[bid];
    int total = sm[SCAN_B - 1];
    __syncthreads();
    int i = bid * SCAN_B + t;
    int v = (i < M) ? g_cnt[i] : 0;
    sm[t] = v;
    __syncthreads();
    for (int d = 1; d < SCAN_B; d <<= 1) {
        int add = (t >= d) ? sm[t - d] : 0;
        __syncthreads();
        sm[t] += add;
        __syncthreads();
    }
    if (i < M) {
        int ex = base + sm[t] - v;
        g_off[i]  = ex;
        g_fill[i] = ex;
    }
    if (bid == 0 && t == 0) g_off[M] = total;
}

__global__ void k_fill(const int* __restrict__ ei, int E) {
    int e = blockIdx.x * blockDim.x + threadIdx.x;
    if (e < E) {
        int s = ei[e];
        int d = ei[E + e];
        int p = atomicAdd(&g_fill[d], 1);
        g_srcs[p] = s;
        g_val[p]  = g_dis[s] * g_dis[d];
    }
}

// ---------------- node GEMM: g_hWh = half(act(A) @ W) ---------------------
// k unrolled x4 with vector A-loads: 12 LDS.128 per 4k instead of 36 LDS.
template <int K, bool FROM_C>
__global__ void __launch_bounds__(256, 2)
k_gemm(const float* __restrict__ X, const float* __restrict__ W,
       const float* __restrict__ bias, int M) {
    extern __shared__ float sm[];
    float* Ws = sm;                 // [K][128]
    float* As = sm + K * FH;        // [64][K]
    const float* A = FROM_C ? g_c : X;

    int t  = threadIdx.x;
    int m0 = blockIdx.x * 64;

    {   // stage W
        const float4* W4  = (const float4*)W;
        float4*       Ws4 = (float4*)Ws;
        #pragma unroll
        for (int i = t; i < K * FH / 4; i += 256) Ws4[i] = W4[i];
    }
    {   // stage A tile with optional fused bias+ReLU
        const int rw = K / 4;
        float4* As4 = (float4*)As;
        for (int i = t; i < 64 * rw; i += 256) {
            int r  = i / rw;
            int c4 = i - r * rw;
            int row = m0 + r;
            float4 v = make_float4(0.f, 0.f, 0.f, 0.f);
            if (row < M) v = *(const float4*)(A + (size_t)row * K + c4 * 4);
            if (FROM_C) {
                float4 b = ((const float4*)bias)[c4];
                v.x = fmaxf(v.x + b.x, 0.f);
                v.y = fmaxf(v.y + b.y, 0.f);
                v.z = fmaxf(v.z + b.z, 0.f);
                v.w = fmaxf(v.w + b.w, 0.f);
            }
            As4[i] = v;
        }
    }
    __syncthreads();

    int cg = t & 31;
    int mg = t >> 5;
    unsigned long long acc2[8][2];
    #pragma unroll
    for (int i = 0; i < 8; i++) { acc2[i][0] = 0ull; acc2[i][1] = 0ull; }

    const float* Ar = As + (size_t)(mg * 8) * K;
    for (int k0 = 0; k0 < K; k0 += 4) {
        float4 a4[8];
        #pragma unroll
        for (int i = 0; i < 8; i++)
            a4[i] = *(const float4*)(Ar + i * K + k0);    // broadcast LDS.128
        #pragma unroll
        for (int kk = 0; kk < 4; kk++) {
            ulonglong2 w = ((const ulonglong2*)(Ws + (k0 + kk) * FH))[cg];
            #pragma unroll
            for (int i = 0; i < 8; i++) {
                float a = (&a4[i].x)[kk];
                unsigned long long aa = pack2(a, a);
                acc2[i][0] = ffma2(aa, w.x, acc2[i][0]);
                acc2[i][1] = ffma2(aa, w.y, acc2[i][1]);
            }
        }
    }

    #pragma unroll
    for (int i = 0; i < 8; i++) {
        int row = m0 + mg * 8 + i;
        if (row < M) {
            float x0, x1, x2, x3;
            unpack2(acc2[i][0], x0, x1);
            unpack2(acc2[i][1], x2, x3);
            __half2 lo = __floats2half2_rn(x0, x1);
            __half2 hi = __floats2half2_rn(x2, x3);
            *(__half2*)(g_hWh + (size_t)row * FH + cg * 4)     = lo;
            *(__half2*)(g_hWh + (size_t)row * FH + cg * 4 + 2) = hi;
        }
    }
}

// ---------------- conv: g_c[dst] = sum_e norm_e * half(g_hWh[src]) --------
// one warp per node; each lane covers 4 features (8 B fp16 gather).
__device__ __forceinline__ float4 ld_h4(const __half* p) {
    uint2 u = *(const uint2*)p;
    __half2 a = *(__half2*)&u.x;
    __half2 b = *(__half2*)&u.y;
    float2 fa = __half22float2(a);
    float2 fb = __half22float2(b);
    return make_float4(fa.x, fa.y, fb.x, fb.y);
}

__global__ void k_conv(int M) {
    int warp = (blockIdx.x * blockDim.x + threadIdx.x) >> 5;
    if (warp >= M) return;
    int lane = threadIdx.x & 31;
    int node = warp;

    float d  = g_dis[node];
    float s0 = d * d;
    float4 h0 = ld_h4(g_hWh + (size_t)node * FH + lane * 4);
    float4 acc = make_float4(s0 * h0.x, s0 * h0.y, s0 * h0.z, s0 * h0.w);

    int e  = g_off[node];
    int e1 = g_off[node + 1];
    while (e < e1) {
        int n = e1 - e; if (n > 32) n = 32;
        int   idx = 0;
        float v   = 0.f;
        if (lane < n) { idx = g_srcs[e + lane]; v = g_val[e + lane]; }
        int j = 0;
        for (; j + 4 <= n; j += 4) {
            int   sA = __shfl_sync(0xffffffffu, idx, j);
            int   sB = __shfl_sync(0xffffffffu, idx, j + 1);
            int   sC = __shfl_sync(0xffffffffu, idx, j + 2);
            int   sD = __shfl_sync(0xffffffffu, idx, j + 3);
            float vA = __shfl_sync(0xffffffffu, v, j);
            float vB = __shfl_sync(0xffffffffu, v, j + 1);
            float vC = __shfl_sync(0xffffffffu, v, j + 2);
            float vD = __shfl_sync(0xffffffffu, v, j + 3);
            float4 hA = ld_h4(g_hWh + (size_t)sA * FH + lane * 4);
            float4 hB = ld_h4(g_hWh + (size_t)sB * FH + lane * 4);
            float4 hC = ld_h4(g_hWh + (size_t)sC * FH + lane * 4);
            float4 hD = ld_h4(g_hWh + (size_t)sD * FH + lane * 4);
            acc.x = fmaf(vA, hA.x, acc.x); acc.y = fmaf(vA, hA.y, acc.y);
            acc.z = fmaf(vA, hA.z, acc.z); acc.w = fmaf(vA, hA.w, acc.w);
            acc.x = fmaf(vB, hB.x, acc.x); acc.y = fmaf(vB, hB.y, acc.y);
            acc.z = fmaf(vB, hB.z, acc.z); acc.w = fmaf(vB, hB.w, acc.w);
            acc.x = fmaf(vC, hC.x, acc.x); acc.y = fmaf(vC, hC.y, acc.y);
            acc.z = fmaf(vC, hC.z, acc.z); acc.w = fmaf(vC, hC.w, acc.w);
            acc.x = fmaf(vD, hD.x, acc.x); acc.y = fmaf(vD, hD.y, acc.y);
            acc.z = fmaf(vD, hD.z, acc.z); acc.w = fmaf(vD, hD.w, acc.w);
        }
        for (; j < n; j++) {
            int   s  = __shfl_sync(0xffffffffu, idx, j);
            float nv = __shfl_sync(0xffffffffu, v, j);
            float4 h = ld_h4(g_hWh + (size_t)s * FH + lane * 4);
            acc.x = fmaf(nv, h.x, acc.x);
            acc.y = fmaf(nv, h.y, acc.y);
            acc.z = fmaf(nv, h.z, acc.z);
            acc.w = fmaf(nv, h.w, acc.w);
        }
        e += n;
    }
    *(float4*)(g_c + (size_t)node * FH + lane * 4) = acc;
}

// ---------------- global mean pool ----------------
__device__ __forceinline__ int lbound(const int* a, int n, int key) {
    int lo = 0, hi = n;
    while (lo < hi) {
        int mid = (lo + hi) >> 1;
        if (a[mid] < key) lo = mid + 1; else hi = mid;
    }
    return lo;
}

__global__ void k_pool(const int* __restrict__ batch,
                       const float* __restrict__ b2, int M) {
    int gi = blockIdx.x;
    int lo = lbound(batch, M, gi);
    int hi = lbound(batch, M, gi + 1);
    int f  = threadIdx.x;                                  // 128
    float s = 0.f;
    for (int i = lo; i < hi; i++) s += g_c[(size_t)i * FH + f];
    int cnt = hi - lo;
    g_pool[gi * FH + f] = (cnt > 0) ? s / (float)cnt + b2[f] : 0.f;
}

// ---------------- MLP head ----------------
__global__ void k_mlp1(const float* __restrict__ Wm1, const float* __restrict__ bm1) {
    __shared__ float gr[FH];
    int gi = blockIdx.x, t = threadIdx.x;                  // 512
    if (t < FH) gr[t] = g_pool[gi * FH + t];
    __syncthreads();
    float s = bm1[t];
    #pragma unroll 8
    for (int k = 0; k < FH; k++) s = fmaf(gr[k], Wm1[k * NHID + t], s);
    g_m1[gi * NHID + t] = fmaxf(s, 0.f);
}

__global__ void k_mlp2(const float* __restrict__ Wm2, const float* __restrict__ bm2,
                       float* __restrict__ out) {
    __shared__ float gr[NHID];
    int gi = blockIdx.x, t = threadIdx.x;                  // 256
    gr[t]       = g_m1[gi * NHID + t];
    gr[t + 256] = g_m1[gi * NHID + t + 256];
    __syncthreads();
    float s = bm2[t];
    #pragma unroll 8
    for (int k = 0; k < NHID; k++) s = fmaf(gr[k], Wm2[k * NOUT + t], s);
    out[gi * NOUT + t] = s;
}

// ---------------- launch ----------------
extern "C" void kernel_launch(void* const* d_in, const int* in_sizes, int n_in,
                              void* d_out, int out_size) {
    const float* x     = (const float*)d_in[0];
    const int*   ei    = (const int*)d_in[1];
    const int*   batch = (const int*)d_in[2];
    const float* W0  = (const float*)d_in[3];
    const float* b0  = (const float*)d_in[4];
    const float* W1  = (const float*)d_in[5];
    const float* b1  = (const float*)d_in[6];
    const float* W2  = (const float*)d_in[7];
    const float* b2  = (const float*)d_in[8];
    const float* Wm1 = (const float*)d_in[9];
    const float* bm1 = (const float*)d_in[10];
    const float* Wm2 = (const float*)d_in[11];
    const float* bm2 = (const float*)d_in[12];
    float* out = (float*)d_out;

    const int M = in_sizes[0] / 64;
    const int E = in_sizes[1] / 2;
    const int G = out_size / NOUT;

    const int smem64  = (64  * FH + 64 * 64)  * 4;   // 48 KB
    const int smem128 = (128 * FH + 64 * 128) * 4;   // 96 KB
    static void* cnt_ptr = nullptr;
    if (!cnt_ptr) {
        cudaFuncSetAttribute(k_gemm<64,  false>, cudaFuncAttributeMaxDynamicSharedMemorySize, smem64);
        cudaFuncSetAttribute(k_gemm<128, true >, cudaFuncAttributeMaxDynamicSharedMemorySize, smem128);
        cudaGetSymbolAddress(&cnt_ptr, g_cnt);
    }

    const int TB = 256;
    int gbE = (E + TB - 1) / TB;
    int gbS = (M + SCAN_B - 1) / SCAN_B;
    int gbG = (M + 63) / 64;
    int gbC = (M + 7) / 8;

    cudaMemsetAsync(cnt_ptr, 0, (size_t)M * sizeof(int));
    k_count <<<gbE, TB>>>(ei, E);
    k_scan1 <<<gbS, SCAN_B>>>(M);
    k_scan23<<<gbS, SCAN_B>>>(M, gbS);
    k_fill  <<<gbE, TB>>>(ei, E);

    k_gemm<64,  false><<<gbG, TB, smem64 >>>(x, W0, nullptr, M);
    k_conv<<<gbC, TB>>>(M);
    k_gemm<128, true ><<<gbG, TB, smem128>>>(nullptr, W1, b0, M);
    k_conv<<<gbC, TB>>>(M);
    k_gemm<128, true ><<<gbG, TB, smem128>>>(nullptr, W2, b1, M);
    k_conv<<<gbC, TB>>>(M);

    k_pool<<<G, FH>>>(batch, b2, M);
    k_mlp1<<<G, NHID>>>(Wm1, bm1);
    k_mlp2<<<G, NOUT>>>(Wm2, bm2, out);
}

// round 8
// speedup vs baseline: 1.6091x; 1.0155x over previous
#include <cuda_runtime.h>
#include <cuda_fp16.h>
#include <cstdint>

// ---------------- problem constants ----------------
#define NMAX   50000
#define NPAD   50048
#define EMAX   800000
#define FH     128
#define NHID   512
#define NOUT   256
#define SCAN_B 256

// ---------------- device scratch (no allocs allowed) --------------
__device__ __half g_hWh[(size_t)NPAD * FH];  // GEMM output fp16 (gather source)
__device__ float  g_c  [(size_t)NPAD * FH];  // conv output fp32
__device__ float  g_dis[NMAX];
__device__ int    g_cnt [NMAX];
__device__ int    g_off [NMAX + 1];
__device__ int    g_fill[NMAX];
__device__ int    g_part[SCAN_B];
__device__ int2   g_edge[EMAX];              // packed (src, __float_as_int(norm))
__device__ float  g_pool[NOUT * FH];
__device__ float  g_m1  [NOUT * NHID];

// ---------------- f32x2 packed-FMA helpers ----------------
__device__ __forceinline__ unsigned long long pack2(float x, float y) {
    unsigned long long r;
    asm("mov.b64 %0, {%1, %2};" : "=l"(r) : "f"(x), "f"(y));
    return r;
}
__device__ __forceinline__ void unpack2(unsigned long long p, float& x, float& y) {
    asm("mov.b64 {%0, %1}, %2;" : "=f"(x), "=f"(y) : "l"(p));
}
__device__ __forceinline__ unsigned long long ffma2(
        unsigned long long a, unsigned long long b, unsigned long long c) {
    unsigned long long d;
    asm("fma.rn.f32x2 %0, %1, %2, %3;" : "=l"(d) : "l"(a), "l"(b), "l"(c));
    return d;
}

// ---------------- graph-prep kernels ----------------
// 4 edges per thread for MLP (E divisible by 4: 800000)
__global__ void k_count(const int* __restrict__ ei, int E) {
    int base = (blockIdx.x * blockDim.x + threadIdx.x) * 4;
    if (base + 3 < E) {
        int4 d4 = *(const int4*)(ei + E + base);
        atomicAdd(&g_cnt[d4.x], 1);
        atomicAdd(&g_cnt[d4.y], 1);
        atomicAdd(&g_cnt[d4.z], 1);
        atomicAdd(&g_cnt[d4.w], 1);
    } else {
        for (int e = base; e < E; e++) atomicAdd(&g_cnt[ei[E + e]], 1);
    }
}

__global__ void k_scan1(int M) {
    __shared__ int red[SCAN_B];
    int t = threadIdx.x;
    int i = blockIdx.x * SCAN_B + t;
    int v = (i < M) ? g_cnt[i] : 0;
    if (i < M) g_dis[i] = rsqrtf((float)(v + 1));      // +1 self loop
    red[t] = v;
    __syncthreads();
    for (int d = SCAN_B / 2; d > 0; d >>= 1) {
        if (t < d) red[t] += red[t + d];
        __syncthreads();
    }
    if (t == 0) g_part[blockIdx.x] = red[0];
}

__global__ void k_scan23(int M, int nb) {
    __shared__ int sm[SCAN_B];
    int t = threadIdx.x, bid = blockIdx.x;
    int pv = (t < nb) ? g_part[t] : 0;
    sm[t] = pv;
    __syncthreads();
    for (int d = 1; d < SCAN_B; d <<= 1) {
        int add = (t >= d) ? sm[t - d] : 0;
        __syncthreads();
        sm[t] += add;
        __syncthreads();
    }
    int base  = sm[bid] - g_part[bid];
    int total = sm[SCAN_B - 1];
    __syncthreads();
    int i = bid * SCAN_B + t;
    int v = (i < M) ? g_cnt[i] : 0;
    sm[t] = v;
    __syncthreads();
    for (int d = 1; d < SCAN_B; d <<= 1) {
        int add = (t >= d) ? sm[t - d] : 0;
        __syncthreads();
        sm[t] += add;
        __syncthreads();
    }
    if (i < M) {
        int ex = base + sm[t] - v;
        g_off[i]  = ex;
        g_fill[i] = ex;
    }
    if (bid == 0 && t == 0) g_off[M] = total;
}

// 4 edges per thread; packed int2 store (src, norm)
__global__ void k_fill(const int* __restrict__ ei, int E) {
    int base = (blockIdx.x * blockDim.x + threadIdx.x) * 4;
    if (base + 3 < E) {
        int4 s4 = *(const int4*)(ei + base);
        int4 d4 = *(const int4*)(ei + E + base);
        float ds0 = g_dis[s4.x], dd0 = g_dis[d4.x];
        float ds1 = g_dis[s4.y], dd1 = g_dis[d4.y];
        float ds2 = g_dis[s4.z], dd2 = g_dis[d4.z];
        float ds3 = g_dis[s4.w], dd3 = g_dis[d4.w];
        int p0 = atomicAdd(&g_fill[d4.x], 1);
        int p1 = atomicAdd(&g_fill[d4.y], 1);
        int p2 = atomicAdd(&g_fill[d4.z], 1);
        int p3 = atomicAdd(&g_fill[d4.w], 1);
        g_edge[p0] = make_int2(s4.x, __float_as_int(ds0 * dd0));
        g_edge[p1] = make_int2(s4.y, __float_as_int(ds1 * dd1));
        g_edge[p2] = make_int2(s4.z, __float_as_int(ds2 * dd2));
        g_edge[p3] = make_int2(s4.w, __float_as_int(ds3 * dd3));
    } else {
        for (int e = base; e < E; e++) {
            int s = ei[e];
            int d = ei[E + e];
            int p = atomicAdd(&g_fill[d], 1);
            g_edge[p] = make_int2(s, __float_as_int(g_dis[s] * g_dis[d]));
        }
    }
}

// ---------------- node GEMM: g_hWh = half(act(A) @ W) ---------------------
template <int K, bool FROM_C>
__global__ void __launch_bounds__(256, 2)
k_gemm(const float* __restrict__ X, const float* __restrict__ W,
       const float* __restrict__ bias, int M) {
    extern __shared__ float sm[];
    float* Ws = sm;                 // [K][128]
    float* As = sm + K * FH;        // [64][K]
    const float* A = FROM_C ? g_c : X;

    int t  = threadIdx.x;
    int m0 = blockIdx.x * 64;

    {   // stage W
        const float4* W4  = (const float4*)W;
        float4*       Ws4 = (float4*)Ws;
        #pragma unroll
        for (int i = t; i < K * FH / 4; i += 256) Ws4[i] = W4[i];
    }
    {   // stage A tile with optional fused bias+ReLU
        const int rw = K / 4;
        float4* As4 = (float4*)As;
        for (int i = t; i < 64 * rw; i += 256) {
            int r  = i / rw;
            int c4 = i - r * rw;
            int row = m0 + r;
            float4 v = make_float4(0.f, 0.f, 0.f, 0.f);
            if (row < M) v = *(const float4*)(A + (size_t)row * K + c4 * 4);
            if (FROM_C) {
                float4 b = ((const float4*)bias)[c4];
                v.x = fmaxf(v.x + b.x, 0.f);
                v.y = fmaxf(v.y + b.y, 0.f);
                v.z = fmaxf(v.z + b.z, 0.f);
                v.w = fmaxf(v.w + b.w, 0.f);
            }
            As4[i] = v;
        }
    }
    __syncthreads();

    int cg = t & 31;
    int mg = t >> 5;
    unsigned long long acc2[8][2];
    #pragma unroll
    for (int i = 0; i < 8; i++) { acc2[i][0] = 0ull; acc2[i][1] = 0ull; }

    const float* Ar = As + (size_t)(mg * 8) * K;
    for (int k0 = 0; k0 < K; k0 += 4) {
        float4 a4[8];
        #pragma unroll
        for (int i = 0; i < 8; i++)
            a4[i] = *(const float4*)(Ar + i * K + k0);    // broadcast LDS.128
        #pragma unroll
        for (int kk = 0; kk < 4; kk++) {
            ulonglong2 w = ((const ulonglong2*)(Ws + (k0 + kk) * FH))[cg];
            #pragma unroll
            for (int i = 0; i < 8; i++) {
                float a = (&a4[i].x)[kk];
                unsigned long long aa = pack2(a, a);
                acc2[i][0] = ffma2(aa, w.x, acc2[i][0]);
                acc2[i][1] = ffma2(aa, w.y, acc2[i][1]);
            }
        }
    }

    #pragma unroll
    for (int i = 0; i < 8; i++) {
        int row = m0 + mg * 8 + i;
        if (row < M) {
            float x0, x1, x2, x3;
            unpack2(acc2[i][0], x0, x1);
            unpack2(acc2[i][1], x2, x3);
            __half2 lo = __floats2half2_rn(x0, x1);
            __half2 hi = __floats2half2_rn(x2, x3);
            uint2 pk = make_uint2(*(unsigned*)&lo, *(unsigned*)&hi);
            *(uint2*)(g_hWh + (size_t)row * FH + cg * 4) = pk;   // STG.64
        }
    }
}

// ---------------- conv: g_c[dst] = sum_e norm_e * half(g_hWh[src]) --------
__device__ __forceinline__ float4 ld_h4(const __half* p) {
    uint2 u = *(const uint2*)p;
    __half2 a = *(__half2*)&u.x;
    __half2 b = *(__half2*)&u.y;
    float2 fa = __half22float2(a);
    float2 fb = __half22float2(b);
    return make_float4(fa.x, fa.y, fb.x, fb.y);
}

__global__ void k_conv(int M) {
    int warp = (blockIdx.x * blockDim.x + threadIdx.x) >> 5;
    if (warp >= M) return;
    int lane = threadIdx.x & 31;
    int node = warp;

    float d  = g_dis[node];
    float s0 = d * d;
    float4 h0 = ld_h4(g_hWh + (size_t)node * FH + lane * 4);
    float4 acc = make_float4(s0 * h0.x, s0 * h0.y, s0 * h0.z, s0 * h0.w);

    int e  = g_off[node];
    int e1 = g_off[node + 1];
    while (e < e1) {
        int n = e1 - e; if (n > 32) n = 32;
        int   idx = 0;
        float v   = 0.f;
        if (lane < n) {
            int2 pk = g_edge[e + lane];
            idx = pk.x;
            v   = __int_as_float(pk.y);
        }
        int j = 0;
        for (; j + 4 <= n; j += 4) {
            int   sA = __shfl_sync(0xffffffffu, idx, j);
            int   sB = __shfl_sync(0xffffffffu, idx, j + 1);
            int   sC = __shfl_sync(0xffffffffu, idx, j + 2);
            int   sD = __shfl_sync(0xffffffffu, idx, j + 3);
            float vA = __shfl_sync(0xffffffffu, v, j);
            float vB = __shfl_sync(0xffffffffu, v, j + 1);
            float vC = __shfl_sync(0xffffffffu, v, j + 2);
            float vD = __shfl_sync(0xffffffffu, v, j + 3);
            float4 hA = ld_h4(g_hWh + (size_t)sA * FH + lane * 4);
            float4 hB = ld_h4(g_hWh + (size_t)sB * FH + lane * 4);
            float4 hC = ld_h4(g_hWh + (size_t)sC * FH + lane * 4);
            float4 hD = ld_h4(g_hWh + (size_t)sD * FH + lane * 4);
            acc.x = fmaf(vA, hA.x, acc.x); acc.y = fmaf(vA, hA.y, acc.y);
            acc.z = fmaf(vA, hA.z, acc.z); acc.w = fmaf(vA, hA.w, acc.w);
            acc.x = fmaf(vB, hB.x, acc.x); acc.y = fmaf(vB, hB.y, acc.y);
            acc.z = fmaf(vB, hB.z, acc.z); acc.w = fmaf(vB, hB.w, acc.w);
            acc.x = fmaf(vC, hC.x, acc.x); acc.y = fmaf(vC, hC.y, acc.y);
            acc.z = fmaf(vC, hC.z, acc.z); acc.w = fmaf(vC, hC.w, acc.w);
            acc.x = fmaf(vD, hD.x, acc.x); acc.y = fmaf(vD, hD.y, acc.y);
            acc.z = fmaf(vD, hD.z, acc.z); acc.w = fmaf(vD, hD.w, acc.w);
        }
        for (; j < n; j++) {
            int   s  = __shfl_sync(0xffffffffu, idx, j);
            float nv = __shfl_sync(0xffffffffu, v, j);
            float4 h = ld_h4(g_hWh + (size_t)s * FH + lane * 4);
            acc.x = fmaf(nv, h.x, acc.x);
            acc.y = fmaf(nv, h.y, acc.y);
            acc.z = fmaf(nv, h.z, acc.z);
            acc.w = fmaf(nv, h.w, acc.w);
        }
        e += n;
    }
    *(float4*)(g_c + (size_t)node * FH + lane * 4) = acc;
}

// ---------------- global mean pool ----------------
__device__ __forceinline__ int lbound(const int* a, int n, int key) {
    int lo = 0, hi = n;
    while (lo < hi) {
        int mid = (lo + hi) >> 1;
        if (a[mid] < key) lo = mid + 1; else hi = mid;
    }
    return lo;
}

__global__ void k_pool(const int* __restrict__ batch,
                       const float* __restrict__ b2, int M) {
    int gi = blockIdx.x;
    int lo = lbound(batch, M, gi);
    int hi = lbound(batch, M, gi + 1);
    int f  = threadIdx.x;                                  // 128
    float s = 0.f;
    for (int i = lo; i < hi; i++) s += g_c[(size_t)i * FH + f];
    int cnt = hi - lo;
    g_pool[gi * FH + f] = (cnt > 0) ? s / (float)cnt + b2[f] : 0.f;
}

// ---------------- MLP head ----------------
__global__ void k_mlp1(const float* __restrict__ Wm1, const float* __restrict__ bm1) {
    __shared__ float gr[FH];
    int gi = blockIdx.x, t = threadIdx.x;                  // 512
    if (t < FH) gr[t] = g_pool[gi * FH + t];
    __syncthreads();
    float s = bm1[t];
    #pragma unroll 8
    for (int k = 0; k < FH; k++) s = fmaf(gr[k], Wm1[k * NHID + t], s);
    g_m1[gi * NHID + t] = fmaxf(s, 0.f);
}

__global__ void k_mlp2(const float* __restrict__ Wm2, const float* __restrict__ bm2,
                       float* __restrict__ out) {
    __shared__ float gr[NHID];
    int gi = blockIdx.x, t = threadIdx.x;                  // 256
    gr[t]       = g_m1[gi * NHID + t];
    gr[t + 256] = g_m1[gi * NHID + t + 256];
    __syncthreads();
    float s = bm2[t];
    #pragma unroll 8
    for (int k = 0; k < NHID; k++) s = fmaf(gr[k], Wm2[k * NOUT + t], s);
    out[gi * NOUT + t] = s;
}

// ---------------- launch ----------------
extern "C" void kernel_launch(void* const* d_in, const int* in_sizes, int n_in,
                              void* d_out, int out_size) {
    const float* x     = (const float*)d_in[0];
    const int*   ei    = (const int*)d_in[1];
    const int*   batch = (const int*)d_in[2];
    const float* W0  = (const float*)d_in[3];
    const float* b0  = (const float*)d_in[4];
    const float* W1  = (const float*)d_in[5];
    const float* b1  = (const float*)d_in[6];
    const float* W2  = (const float*)d_in[7];
    const float* b2  = (const float*)d_in[8];
    const float* Wm1 = (const float*)d_in[9];
    const float* bm1 = (const float*)d_in[10];
    const float* Wm2 = (const float*)d_in[11];
    const float* bm2 = (const float*)d_in[12];
    float* out = (float*)d_out;

    const int M = in_sizes[0] / 64;
    const int E = in_sizes[1] / 2;
    const int G = out_size / NOUT;

    const int smem64  = (64  * FH + 64 * 64)  * 4;   // 48 KB
    const int smem128 = (128 * FH + 64 * 128) * 4;   // 96 KB
    static void* cnt_ptr = nullptr;
    if (!cnt_ptr) {
        cudaFuncSetAttribute(k_gemm<64,  false>, cudaFuncAttributeMaxDynamicSharedMemorySize, smem64);
        cudaFuncSetAttribute(k_gemm<128, true >, cudaFuncAttributeMaxDynamicSharedMemorySize, smem128);
        cudaGetSymbolAddress(&cnt_ptr, g_cnt);
    }

    const int TB = 256;
    int gbE4 = (E / 4 + TB - 1) / TB;      // 4 edges/thread
    int gbS = (M + SCAN_B - 1) / SCAN_B;
    int gbG = (M + 63) / 64;
    int gbC = (M + 7) / 8;

    cudaMemsetAsync(cnt_ptr, 0, (size_t)M * sizeof(int));
    // layer-0 GEMM first: independent of graph prep; also aims ncu -s 5 at k_conv
    k_gemm<64,  false><<<gbG, TB, smem64 >>>(x, W0, nullptr, M);   // k0
    k_count <<<gbE4, TB>>>(ei, E);                                 // k1
    k_scan1 <<<gbS, SCAN_B>>>(M);                                  // k2
    k_scan23<<<gbS, SCAN_B>>>(M, gbS);                             // k3
    k_fill  <<<gbE4, TB>>>(ei, E);                                 // k4

    k_conv<<<gbC, TB>>>(M);                                        // k5 <- ncu
    k_gemm<128, true ><<<gbG, TB, smem128>>>(nullptr, W1, b0, M);
    k_conv<<<gbC, TB>>>(M);
    k_gemm<128, true ><<<gbG, TB, smem128>>>(nullptr, W2, b1, M);
    k_conv<<<gbC, TB>>>(M);

    k_pool<<<G, FH>>>(batch, b2, M);
    k_mlp1<<<G, NHID>>>(Wm1, bm1);
    k_mlp2<<<G, NOUT>>>(Wm2, bm2, out);
}

// round 9
// speedup vs baseline: 1.8824x; 1.1698x over previous
#include <cuda_runtime.h>
#include <cuda_fp16.h>
#include <cstdint>

// ---------------- problem constants ----------------
#define NMAX   50000
#define NPAD   50048
#define EMAX   800000
#define FH     128
#define NHID   512
#define NOUT   256
#define SCAN_B 256

// ---------------- device scratch (no allocs allowed) --------------
__device__ __half g_hWh[(size_t)NPAD * FH];  // GEMM output fp16 (gather source)
__device__ float  g_c  [(size_t)NPAD * FH];  // conv output fp32
__device__ float  g_dis[NMAX];
__device__ int    g_cnt [NMAX];
__device__ int    g_off [NMAX + 1];
__device__ int    g_fill[NMAX];
__device__ int    g_part[SCAN_B];
__device__ int2   g_edge[EMAX];              // packed (src, __float_as_int(norm))
__device__ float  g_pool[NOUT * FH];
__device__ float  g_m1  [NOUT * NHID];

// ---------------- graph-prep kernels ----------------
__global__ void k_count(const int* __restrict__ ei, int E) {
    int base = (blockIdx.x * blockDim.x + threadIdx.x) * 4;
    if (base + 3 < E) {
        int4 d4 = *(const int4*)(ei + E + base);
        atomicAdd(&g_cnt[d4.x], 1);
        atomicAdd(&g_cnt[d4.y], 1);
        atomicAdd(&g_cnt[d4.z], 1);
        atomicAdd(&g_cnt[d4.w], 1);
    } else {
        for (int e = base; e < E; e++) atomicAdd(&g_cnt[ei[E + e]], 1);
    }
}

__global__ void k_scan1(int M) {
    __shared__ int red[SCAN_B];
    int t = threadIdx.x;
    int i = blockIdx.x * SCAN_B + t;
    int v = (i < M) ? g_cnt[i] : 0;
    if (i < M) g_dis[i] = rsqrtf((float)(v + 1));      // +1 self loop
    red[t] = v;
    __syncthreads();
    for (int d = SCAN_B / 2; d > 0; d >>= 1) {
        if (t < d) red[t] += red[t + d];
        __syncthreads();
    }
    if (t == 0) g_part[blockIdx.x] = red[0];
}

__global__ void k_scan23(int M, int nb) {
    __shared__ int sm[SCAN_B];
    int t = threadIdx.x, bid = blockIdx.x;
    int pv = (t < nb) ? g_part[t] : 0;
    sm[t] = pv;
    __syncthreads();
    for (int d = 1; d < SCAN_B; d <<= 1) {
        int add = (t >= d) ? sm[t - d] : 0;
        __syncthreads();
        sm[t] += add;
        __syncthreads();
    }
    int base  = sm[bid] - g_part[bid];
    int total = sm[SCAN_B - 1];
    __syncthreads();
    int i = bid * SCAN_B + t;
    int v = (i < M) ? g_cnt[i] : 0;
    sm[t] = v;
    __syncthreads();
    for (int d = 1; d < SCAN_B; d <<= 1) {
        int add = (t >= d) ? sm[t - d] : 0;
        __syncthreads();
        sm[t] += add;
        __syncthreads();
    }
    if (i < M) {
        int ex = base + sm[t] - v;
        g_off[i]  = ex;
        g_fill[i] = ex;
    }
    if (bid == 0 && t == 0) g_off[M] = total;
}

__global__ void k_fill(const int* __restrict__ ei, int E) {
    int base = (blockIdx.x * blockDim.x + threadIdx.x) * 4;
    if (base + 3 < E) {
        int4 s4 = *(const int4*)(ei + base);
        int4 d4 = *(const int4*)(ei + E + base);
        float ds0 = g_dis[s4.x], dd0 = g_dis[d4.x];
        float ds1 = g_dis[s4.y], dd1 = g_dis[d4.y];
        float ds2 = g_dis[s4.z], dd2 = g_dis[d4.z];
        float ds3 = g_dis[s4.w], dd3 = g_dis[d4.w];
        int p0 = atomicAdd(&g_fill[d4.x], 1);
        int p1 = atomicAdd(&g_fill[d4.y], 1);
        int p2 = atomicAdd(&g_fill[d4.z], 1);
        int p3 = atomicAdd(&g_fill[d4.w], 1);
        g_edge[p0] = make_int2(s4.x, __float_as_int(ds0 * dd0));
        g_edge[p1] = make_int2(s4.y, __float_as_int(ds1 * dd1));
        g_edge[p2] = make_int2(s4.z, __float_as_int(ds2 * dd2));
        g_edge[p3] = make_int2(s4.w, __float_as_int(ds3 * dd3));
    } else {
        for (int e = base; e < E; e++) {
            int s = ei[e];
            int d = ei[E + e];
            int p = atomicAdd(&g_fill[d], 1);
            g_edge[p] = make_int2(s, __float_as_int(g_dis[s] * g_dis[d]));
        }
    }
}

// ---------------- tensor-core node GEMM: g_hWh = half(act(A) @ W) ---------
// 128x128 block tile, 8 warps (4 m x 2 n), warp tile 32x64, mma.m16n8k16.
// As[m][k] and Bs[n][k] (W transposed) in smem, +8-half row pad; all
// fragments are direct conflict-free half2 LDS (no ldmatrix needed).
template <int K, bool FROM_C>
__global__ void __launch_bounds__(256, 2)
k_gemm_t(const float* __restrict__ X, const float* __restrict__ W,
         const float* __restrict__ bias, int M) {
    extern __shared__ __half sh[];
    const int LDA = K + 8;
    __half* As = sh;                    // [128][LDA]
    __half* Bs = sh + 128 * LDA;        // [128][LDA]  (Bs[n][k] = W[k][n])
    int t  = threadIdx.x;
    int m0 = blockIdx.x * 128;
    const float* A = FROM_C ? g_c : X;

    // stage W transposed
    {
        const float4* W4 = (const float4*)W;          // (k, n4) tiles
        for (int i = t; i < K * 32; i += 256) {
            int k  = i >> 5;
            int n4 = (i & 31) << 2;
            float4 w = W4[i];
            Bs[(n4 + 0) * LDA + k] = __float2half(w.x);
            Bs[(n4 + 1) * LDA + k] = __float2half(w.y);
            Bs[(n4 + 2) * LDA + k] = __float2half(w.z);
            Bs[(n4 + 3) * LDA + k] = __float2half(w.w);
        }
    }
    // stage A (fp32 -> fp16, optional fused bias+ReLU), 8 cols/iter
    {
        const int rw = K / 8;
        for (int i = t; i < 128 * rw; i += 256) {
            int r  = i / rw;
            int c8 = (i - r * rw) * 8;
            int row = m0 + r;
            float4 v0 = make_float4(0.f, 0.f, 0.f, 0.f), v1 = v0;
            if (row < M) {
                v0 = *(const float4*)(A + (size_t)row * K + c8);
                v1 = *(const float4*)(A + (size_t)row * K + c8 + 4);
            }
            if (FROM_C) {
                float4 ba = ((const float4*)bias)[c8 >> 2];
                float4 bb = ((const float4*)bias)[(c8 >> 2) + 1];
                v0.x = fmaxf(v0.x + ba.x, 0.f); v0.y = fmaxf(v0.y + ba.y, 0.f);
                v0.z = fmaxf(v0.z + ba.z, 0.f); v0.w = fmaxf(v0.w + ba.w, 0.f);
                v1.x = fmaxf(v1.x + bb.x, 0.f); v1.y = fmaxf(v1.y + bb.y, 0.f);
                v1.z = fmaxf(v1.z + bb.z, 0.f); v1.w = fmaxf(v1.w + bb.w, 0.f);
            }
            __half2 h0 = __floats2half2_rn(v0.x, v0.y);
            __half2 h1 = __floats2half2_rn(v0.z, v0.w);
            __half2 h2 = __floats2half2_rn(v1.x, v1.y);
            __half2 h3 = __floats2half2_rn(v1.z, v1.w);
            uint4 pk = make_uint4(*(unsigned*)&h0, *(unsigned*)&h1,
                                  *(unsigned*)&h2, *(unsigned*)&h3);
            *(uint4*)(As + r * LDA + c8) = pk;
        }
    }
    __syncthreads();

    int lane = t & 31;
    int wid  = t >> 5;
    int wm = wid & 3;          // 0..3 -> 32 rows each
    int wn = wid >> 2;         // 0..1 -> 64 cols each
    int g  = lane >> 2;        // 0..7
    int tg = lane & 3;         // 0..3

    float c[2][8][4];
    #pragma unroll
    for (int mi = 0; mi < 2; mi++)
        #pragma unroll
        for (int ni = 0; ni < 8; ni++)
            #pragma unroll
            for (int q = 0; q < 4; q++) c[mi][ni][q] = 0.f;

    #pragma unroll
    for (int k0 = 0; k0 < K; k0 += 16) {
        uint32_t a[2][4], b[8][2];
        #pragma unroll
        for (int mi = 0; mi < 2; mi++) {
            int r = wm * 32 + mi * 16 + g;
            const __half* p = As + r * LDA + k0 + tg * 2;
            a[mi][0] = *(const uint32_t*)p;
            a[mi][1] = *(const uint32_t*)(p + 8 * LDA);
            a[mi][2] = *(const uint32_t*)(p + 8);
            a[mi][3] = *(const uint32_t*)(p + 8 * LDA + 8);
        }
        #pragma unroll
        for (int ni = 0; ni < 8; ni++) {
            int n = wn * 64 + ni * 8 + g;
            const __half* p = Bs + n * LDA + k0 + tg * 2;
            b[ni][0] = *(const uint32_t*)p;
            b[ni][1] = *(const uint32_t*)(p + 8);
        }
        #pragma unroll
        for (int mi = 0; mi < 2; mi++)
            #pragma unroll
            for (int ni = 0; ni < 8; ni++)
                asm volatile(
                    "mma.sync.aligned.m16n8k16.row.col.f32.f16.f16.f32 "
                    "{%0,%1,%2,%3}, {%4,%5,%6,%7}, {%8,%9}, {%0,%1,%2,%3};"
                    : "+f"(c[mi][ni][0]), "+f"(c[mi][ni][1]),
                      "+f"(c[mi][ni][2]), "+f"(c[mi][ni][3])
                    : "r"(a[mi][0]), "r"(a[mi][1]), "r"(a[mi][2]), "r"(a[mi][3]),
                      "r"(b[ni][0]), "r"(b[ni][1]));
    }

    // epilogue: c0=C[g][2tg] c1=C[g][2tg+1] c2=C[g+8][2tg] c3=C[g+8][2tg+1]
    #pragma unroll
    for (int mi = 0; mi < 2; mi++) {
        int r0 = m0 + wm * 32 + mi * 16 + g;     // < NPAD always
        #pragma unroll
        for (int ni = 0; ni < 8; ni++) {
            int col = wn * 64 + ni * 8 + tg * 2;
            __half2 lo = __floats2half2_rn(c[mi][ni][0], c[mi][ni][1]);
            __half2 hi = __floats2half2_rn(c[mi][ni][2], c[mi][ni][3]);
            *(__half2*)(g_hWh + (size_t)r0 * FH + col)        = lo;
            *(__half2*)(g_hWh + (size_t)(r0 + 8) * FH + col)  = hi;
        }
    }
}

// ---------------- conv: g_c[dst] = sum_e norm_e * half(g_hWh[src]) --------
__device__ __forceinline__ float4 ld_h4(const __half* p) {
    uint2 u = *(const uint2*)p;
    __half2 a = *(__half2*)&u.x;
    __half2 b = *(__half2*)&u.y;
    float2 fa = __half22float2(a);
    float2 fb = __half22float2(b);
    return make_float4(fa.x, fa.y, fb.x, fb.y);
}

__global__ void k_conv(int M) {
    int warp = (blockIdx.x * blockDim.x + threadIdx.x) >> 5;
    if (warp >= M) return;
    int lane = threadIdx.x & 31;
    int node = warp;

    float d  = g_dis[node];
    float s0 = d * d;
    float4 h0 = ld_h4(g_hWh + (size_t)node * FH + lane * 4);
    float4 acc = make_float4(s0 * h0.x, s0 * h0.y, s0 * h0.z, s0 * h0.w);

    int e  = g_off[node];
    int e1 = g_off[node + 1];
    while (e < e1) {
        int n = e1 - e; if (n > 32) n = 32;
        int   idx = 0;
        float v   = 0.f;
        if (lane < n) {
            int2 pk = g_edge[e + lane];
            idx = pk.x;
            v   = __int_as_float(pk.y);
        }
        int j = 0;
        for (; j + 4 <= n; j += 4) {
            int   sA = __shfl_sync(0xffffffffu, idx, j);
            int   sB = __shfl_sync(0xffffffffu, idx, j + 1);
            int   sC = __shfl_sync(0xffffffffu, idx, j + 2);
            int   sD = __shfl_sync(0xffffffffu, idx, j + 3);
            float vA = __shfl_sync(0xffffffffu, v, j);
            float vB = __shfl_sync(0xffffffffu, v, j + 1);
            float vC = __shfl_sync(0xffffffffu, v, j + 2);
            float vD = __shfl_sync(0xffffffffu, v, j + 3);
            float4 hA = ld_h4(g_hWh + (size_t)sA * FH + lane * 4);
            float4 hB = ld_h4(g_hWh + (size_t)sB * FH + lane * 4);
            float4 hC = ld_h4(g_hWh + (size_t)sC * FH + lane * 4);
            float4 hD = ld_h4(g_hWh + (size_t)sD * FH + lane * 4);
            acc.x = fmaf(vA, hA.x, acc.x); acc.y = fmaf(vA, hA.y, acc.y);
            acc.z = fmaf(vA, hA.z, acc.z); acc.w = fmaf(vA, hA.w, acc.w);
            acc.x = fmaf(vB, hB.x, acc.x); acc.y = fmaf(vB, hB.y, acc.y);
            acc.z = fmaf(vB, hB.z, acc.z); acc.w = fmaf(vB, hB.w, acc.w);
            acc.x = fmaf(vC, hC.x, acc.x); acc.y = fmaf(vC, hC.y, acc.y);
            acc.z = fmaf(vC, hC.z, acc.z); acc.w = fmaf(vC, hC.w, acc.w);
            acc.x = fmaf(vD, hD.x, acc.x); acc.y = fmaf(vD, hD.y, acc.y);
            acc.z = fmaf(vD, hD.z, acc.z); acc.w = fmaf(vD, hD.w, acc.w);
        }
        for (; j < n; j++) {
            int   s  = __shfl_sync(0xffffffffu, idx, j);
            float nv = __shfl_sync(0xffffffffu, v, j);
            float4 h = ld_h4(g_hWh + (size_t)s * FH + lane * 4);
            acc.x = fmaf(nv, h.x, acc.x);
            acc.y = fmaf(nv, h.y, acc.y);
            acc.z = fmaf(nv, h.z, acc.z);
            acc.w = fmaf(nv, h.w, acc.w);
        }
        e += n;
    }
    *(float4*)(g_c + (size_t)node * FH + lane * 4) = acc;
}

// ---------------- global mean pool ----------------
__device__ __forceinline__ int lbound(const int* a, int n, int key) {
    int lo = 0, hi = n;
    while (lo < hi) {
        int mid = (lo + hi) >> 1;
        if (a[mid] < key) lo = mid + 1; else hi = mid;
    }
    return lo;
}

__global__ void k_pool(const int* __restrict__ batch,
                       const float* __restrict__ b2, int M) {
    int gi = blockIdx.x;
    int lo = lbound(batch, M, gi);
    int hi = lbound(batch, M, gi + 1);
    int f  = threadIdx.x;                                  // 128
    float s = 0.f;
    for (int i = lo; i < hi; i++) s += g_c[(size_t)i * FH + f];
    int cnt = hi - lo;
    g_pool[gi * FH + f] = (cnt > 0) ? s / (float)cnt + b2[f] : 0.f;
}

// ---------------- MLP head ----------------
__global__ void k_mlp1(const float* __restrict__ Wm1, const float* __restrict__ bm1) {
    __shared__ float gr[FH];
    int gi = blockIdx.x, t = threadIdx.x;                  // 512
    if (t < FH) gr[t] = g_pool[gi * FH + t];
    __syncthreads();
    float s = bm1[t];
    #pragma unroll 8
    for (int k = 0; k < FH; k++) s = fmaf(gr[k], Wm1[k * NHID + t], s);
    g_m1[gi * NHID + t] = fmaxf(s, 0.f);
}

__global__ void k_mlp2(const float* __restrict__ Wm2, const float* __restrict__ bm2,
                       float* __restrict__ out) {
    __shared__ float gr[NHID];
    int gi = blockIdx.x, t = threadIdx.x;                  // 256
    gr[t]       = g_m1[gi * NHID + t];
    gr[t + 256] = g_m1[gi * NHID + t + 256];
    __syncthreads();
    float s = bm2[t];
    #pragma unroll 8
    for (int k = 0; k < NHID; k++) s = fmaf(gr[k], Wm2[k * NOUT + t], s);
    out[gi * NOUT + t] = s;
}

// ---------------- launch ----------------
extern "C" void kernel_launch(void* const* d_in, const int* in_sizes, int n_in,
                              void* d_out, int out_size) {
    const float* x     = (const float*)d_in[0];
    const int*   ei    = (const int*)d_in[1];
    const int*   batch = (const int*)d_in[2];
    const float* W0  = (const float*)d_in[3];
    const float* b0  = (const float*)d_in[4];
    const float* W1  = (const float*)d_in[5];
    const float* b1  = (const float*)d_in[6];
    const float* W2  = (const float*)d_in[7];
    const float* b2  = (const float*)d_in[8];
    const float* Wm1 = (const float*)d_in[9];
    const float* bm1 = (const float*)d_in[10];
    const float* Wm2 = (const float*)d_in[11];
    const float* bm2 = (const float*)d_in[12];
    float* out = (float*)d_out;

    const int M = in_sizes[0] / 64;
    const int E = in_sizes[1] / 2;
    const int G = out_size / NOUT;

    const int smem64  = 2 * 128 * (64  + 8) * 2;   // 36,864 B
    const int smem128 = 2 * 128 * (128 + 8) * 2;   // 69,632 B
    static void* cnt_ptr = nullptr;
    if (!cnt_ptr) {
        cudaFuncSetAttribute(k_gemm_t<64,  false>, cudaFuncAttributeMaxDynamicSharedMemorySize, smem64);
        cudaFuncSetAttribute(k_gemm_t<128, true >, cudaFuncAttributeMaxDynamicSharedMemorySize, smem128);
        cudaGetSymbolAddress(&cnt_ptr, g_cnt);
    }

    const int TB = 256;
    int gbE4 = (E / 4 + TB - 1) / TB;
    int gbS  = (M + SCAN_B - 1) / SCAN_B;
    int gbG  = NPAD / 128;                 // 391 (M-pad covered, guarded inside)
    int gbC  = (M + 7) / 8;

    cudaMemsetAsync(cnt_ptr, 0, (size_t)M * sizeof(int));
    k_count <<<gbE4, TB>>>(ei, E);                                 // 0
    k_scan1 <<<gbS, SCAN_B>>>(M);                                  // 1
    k_scan23<<<gbS, SCAN_B>>>(M, gbS);                             // 2
    k_fill  <<<gbE4, TB>>>(ei, E);                                 // 3 <- ncu
    k_gemm_t<64,  false><<<gbG, TB, smem64 >>>(x, W0, nullptr, M); // 4
    k_conv<<<gbC, TB>>>(M);                                        // 5
    k_gemm_t<128, true ><<<gbG, TB, smem128>>>(nullptr, W1, b0, M);
    k_conv<<<gbC, TB>>>(M);
    k_gemm_t<128, true ><<<gbG, TB, smem128>>>(nullptr, W2, b1, M);
    k_conv<<<gbC, TB>>>(M);

    k_pool<<<G, FH>>>(batch, b2, M);
    k_mlp1<<<G, NHID>>>(Wm1, bm1);
    k_mlp2<<<G, NOUT>>>(Wm2, bm2, out);
}